// round 5
// baseline (speedup 1.0000x reference)
#include <cuda_runtime.h>
#include <cstddef>

// MirrorAttention: B=8, C=512, H=W=48 (N=2304), MID=128
//   f_a = BNReLU(Wa x),  f_v = BNReLU(Wv x_v),  f_h = BNReLU(Wv x_h)
//   g_av = Wgav x + b,   g_ah = Wgah x + b
//   per pass t in {ah (-> o_h, first half), av (-> o_v, second half)}:
//     S = scale * f_q^T f_a  -> A = softmax_rows(S)   (170MB scratch reused)
//     o_mid = g A
//     out = Wf o_mid + bf + x
// All fp32. SGEMM: 128x128x16 tiles, 8x8 microtile, 256 thr,
// double-buffered smem with register-staged prefetch (1 bar.sync / k-tile).

#define BB 8
#define CC 512
#define NN 2304
#define MD 128

static __device__ float d_fa [BB * MD * NN];
static __device__ float d_fv [BB * MD * NN];
static __device__ float d_fh [BB * MD * NN];
static __device__ float d_gav[BB * MD * NN];
static __device__ float d_gah[BB * MD * NN];
static __device__ float d_om [BB * MD * NN];
static __device__ float d_Am [(size_t)BB * NN * NN];   // 169.9 MB scratch

// --- tile load helpers (2 x float4 per thread per operand) ------------------
__device__ __forceinline__ void ldA_T(const float* __restrict__ A, int M,
                                      int m0, int k0, int tid,
                                      float4& r0, float4& r1)
{
    // A is [K, M] row-major: straight copy of a 16x128 slab.
    int s = tid;
    r0 = *(const float4*)&A[(size_t)(k0 + (s >> 5)) * M + m0 + ((s & 31) << 2)];
    s = tid + 256;
    r1 = *(const float4*)&A[(size_t)(k0 + (s >> 5)) * M + m0 + ((s & 31) << 2)];
}

__device__ __forceinline__ void ldA_N(const float* __restrict__ A, int K,
                                      int m0, int k0, int tid,
                                      float4& r0, float4& r1)
{
    // A is [M, K] row-major: each thread grabs 4 consecutive k of one m row.
    int s = tid;
    r0 = *(const float4*)&A[(size_t)(m0 + (s >> 2)) * K + k0 + ((s & 3) << 2)];
    s = tid + 256;
    r1 = *(const float4*)&A[(size_t)(m0 + (s >> 2)) * K + k0 + ((s & 3) << 2)];
}

__device__ __forceinline__ void stA_T(float (*As)[128], int tid,
                                      const float4& r0, const float4& r1)
{
    int s = tid;
    *(float4*)&As[s >> 5][(s & 31) << 2] = r0;
    s = tid + 256;
    *(float4*)&As[s >> 5][(s & 31) << 2] = r1;
}

__device__ __forceinline__ void stA_N(float (*As)[128], int tid,
                                      const float4& r0, const float4& r1)
{
    int s = tid, r = s >> 2, kq = (s & 3) << 2;
    As[kq + 0][r] = r0.x; As[kq + 1][r] = r0.y;
    As[kq + 2][r] = r0.z; As[kq + 3][r] = r0.w;
    s = tid + 256; r = s >> 2; kq = (s & 3) << 2;
    As[kq + 0][r] = r1.x; As[kq + 1][r] = r1.y;
    As[kq + 2][r] = r1.z; As[kq + 3][r] = r1.w;
}

// ---------------------------------------------------------------------------
// Tiled SGEMM: C[b] = epi( A[b] (or A[b]^T) * B[b] )
// A row-major [M,K] (or [K,M] when TA), B row-major [K,N], C row-major [M,N].
// MODE: 0 = +bias[m]
//       1 = BN-ReLU: relu(acc*s + bias[m]*s + beta[m]), s = gamma[m]/sqrt(1+eps)
//       2 = +bias[m] + resid[m*N+n]
//       3 = *alpha
//       4 = plain store
// Requires M%128==0, N%128==0, K%16==0 (true for all call sites).
// ---------------------------------------------------------------------------
template<int MODE, bool TA>
__global__ void __launch_bounds__(256)
sgemm128(const float* __restrict__ A, size_t sA,
         const float* __restrict__ Bm, size_t sB,
         float* __restrict__ C, size_t sC,
         int M, int N, int K,
         const float* __restrict__ bias,
         const float* __restrict__ gam,
         const float* __restrict__ bet,
         const float* __restrict__ resid, size_t sR,
         float alpha)
{
    __shared__ float As[2][16][128];
    __shared__ float Bs[2][16][128];

    const int b = blockIdx.z;
    A  += (size_t)b * sA;
    Bm += (size_t)b * sB;
    C  += (size_t)b * sC;
    if (MODE == 2) resid += (size_t)b * sR;

    const int m0 = blockIdx.y * 128;
    const int n0 = blockIdx.x * 128;
    const int tid = threadIdx.x;
    const int ty = tid >> 4;   // 0..15 (m dir)
    const int tx = tid & 15;   // 0..15 (n dir)

    float acc[8][8];
#pragma unroll
    for (int i = 0; i < 8; ++i)
#pragma unroll
        for (int j = 0; j < 8; ++j) acc[i][j] = 0.f;

    float4 a0, a1, b0, b1;
    int buf = 0;

    // Prologue: tile 0 -> smem[0]
    if (TA) ldA_T(A, M, m0, 0, tid, a0, a1);
    else    ldA_N(A, K, m0, 0, tid, a0, a1);
    ldA_T(Bm, N, n0, 0, tid, b0, b1);          // B always [K,N]: slab copy
    if (TA) stA_T(As[0], tid, a0, a1);
    else    stA_N(As[0], tid, a0, a1);
    stA_T(Bs[0], tid, b0, b1);
    __syncthreads();

    for (int k0 = 0; k0 < K; k0 += 16) {
        const bool has_next = (k0 + 16) < K;
        if (has_next) {
            if (TA) ldA_T(A, M, m0, k0 + 16, tid, a0, a1);
            else    ldA_N(A, K, m0, k0 + 16, tid, a0, a1);
            ldA_T(Bm, N, n0, k0 + 16, tid, b0, b1);
        }

#pragma unroll
        for (int k = 0; k < 16; ++k) {
            float ra[8], rb[8];
#pragma unroll
            for (int i = 0; i < 8; ++i) ra[i] = As[buf][k][ty * 8 + i];
#pragma unroll
            for (int j = 0; j < 8; ++j) rb[j] = Bs[buf][k][tx * 8 + j];
#pragma unroll
            for (int i = 0; i < 8; ++i)
#pragma unroll
                for (int j = 0; j < 8; ++j)
                    acc[i][j] = fmaf(ra[i], rb[j], acc[i][j]);
        }

        if (has_next) {
            if (TA) stA_T(As[buf ^ 1], tid, a0, a1);
            else    stA_N(As[buf ^ 1], tid, a0, a1);
            stA_T(Bs[buf ^ 1], tid, b0, b1);
            __syncthreads();
            buf ^= 1;
        }
    }

#pragma unroll
    for (int i = 0; i < 8; ++i) {
        const int m = m0 + ty * 8 + i;
        float sc = 1.f, bs = 0.f;
        if (MODE == 0 || MODE == 2) bs = bias[m];
        if (MODE == 1) {
            sc = gam[m] * rsqrtf(1.f + 1e-5f);
            bs = fmaf(bias[m], sc, bet[m]);
        }
#pragma unroll
        for (int j = 0; j < 8; ++j) {
            const int n = n0 + tx * 8 + j;
            float v = acc[i][j];
            if (MODE == 1)      v = fmaxf(fmaf(v, sc, bs), 0.f);
            else if (MODE == 0) v += bs;
            else if (MODE == 2) v += bs + resid[(size_t)m * N + n];
            else if (MODE == 3) v *= alpha;
            C[(size_t)m * N + n] = v;
        }
    }
}

// ---------------------------------------------------------------------------
// Row softmax in place: one block per row of 2304 (= 9 * 256) elements.
// ---------------------------------------------------------------------------
__global__ void __launch_bounds__(256)
softmax_rows(float* __restrict__ Am)
{
    float* p = Am + (size_t)blockIdx.x * NN;
    const int t = threadIdx.x;

    float v[9];
    float mx = -3.4e38f;
#pragma unroll
    for (int r = 0; r < 9; ++r) {
        v[r] = p[t + (r << 8)];
        mx = fmaxf(mx, v[r]);
    }
    __shared__ float red[8];
#pragma unroll
    for (int o = 16; o > 0; o >>= 1)
        mx = fmaxf(mx, __shfl_xor_sync(0xffffffffu, mx, o));
    if ((t & 31) == 0) red[t >> 5] = mx;
    __syncthreads();
    float m2 = red[0];
#pragma unroll
    for (int w = 1; w < 8; ++w) m2 = fmaxf(m2, red[w]);

    float sum = 0.f;
#pragma unroll
    for (int r = 0; r < 9; ++r) {
        v[r] = __expf(v[r] - m2);
        sum += v[r];
    }
#pragma unroll
    for (int o = 16; o > 0; o >>= 1)
        sum += __shfl_xor_sync(0xffffffffu, sum, o);
    __syncthreads();
    if ((t & 31) == 0) red[t >> 5] = sum;
    __syncthreads();
    float s2 = 0.f;
#pragma unroll
    for (int w = 0; w < 8; ++w) s2 += red[w];
    const float inv = 1.f / s2;

#pragma unroll
    for (int r = 0; r < 9; ++r) p[t + (r << 8)] = v[r] * inv;
}

// ---------------------------------------------------------------------------

extern "C" void kernel_launch(void* const* d_in, const int* in_sizes, int n_in,
                              void* d_out, int out_size)
{
    const float* x    = (const float*)d_in[0];
    const float* x_h  = (const float*)d_in[1];
    const float* x_v  = (const float*)d_in[2];
    const float* Wa   = (const float*)d_in[3];
    const float* ba   = (const float*)d_in[4];
    const float* ga   = (const float*)d_in[5];
    const float* ta   = (const float*)d_in[6];
    const float* Wv   = (const float*)d_in[7];
    const float* bv   = (const float*)d_in[8];
    const float* gv   = (const float*)d_in[9];
    const float* tv   = (const float*)d_in[10];
    const float* Wgav = (const float*)d_in[11];
    const float* bgav = (const float*)d_in[12];
    const float* Wgah = (const float*)d_in[13];
    const float* bgah = (const float*)d_in[14];
    const float* Wfav = (const float*)d_in[15];
    const float* bfav = (const float*)d_in[16];
    const float* Wfah = (const float*)d_in[17];
    const float* bfah = (const float*)d_in[18];
    float* out = (float*)d_out;

    float *fa, *fv, *fh, *gav, *gah, *om, *Am;
    cudaGetSymbolAddress((void**)&fa,  d_fa);
    cudaGetSymbolAddress((void**)&fv,  d_fv);
    cudaGetSymbolAddress((void**)&fh,  d_fh);
    cudaGetSymbolAddress((void**)&gav, d_gav);
    cudaGetSymbolAddress((void**)&gah, d_gah);
    cudaGetSymbolAddress((void**)&om,  d_om);
    cudaGetSymbolAddress((void**)&Am,  d_Am);

    const size_t sX  = (size_t)CC * NN;   // per-batch x stride
    const size_t sF  = (size_t)MD * NN;   // per-batch f/g/o_mid stride
    const size_t sAm = (size_t)NN * NN;   // per-batch attention stride
    const size_t halfOut = (size_t)BB * CC * NN;
    const float alpha = 0.08838834764831845f;  // 128^-0.5

    dim3 blk(256);
    dim3 gConv (NN / 128, 1, BB);          // M=128
    dim3 gScore(NN / 128, NN / 128, BB);   // M=N=2304
    dim3 gApply(NN / 128, 1, BB);          // M=128, K=2304
    dim3 gOut  (NN / 128, CC / 128, BB);   // M=512

    // Phase 1: input convs
    sgemm128<1, false><<<gConv, blk>>>(Wa, 0, x,   sX, fa,  sF, MD, NN, CC, ba,   ga, ta, nullptr, 0, 0.f);
    sgemm128<1, false><<<gConv, blk>>>(Wv, 0, x_v, sX, fv,  sF, MD, NN, CC, bv,   gv, tv, nullptr, 0, 0.f);
    sgemm128<1, false><<<gConv, blk>>>(Wv, 0, x_h, sX, fh,  sF, MD, NN, CC, bv,   gv, tv, nullptr, 0, 0.f);
    sgemm128<0, false><<<gConv, blk>>>(Wgav, 0, x, sX, gav, sF, MD, NN, CC, bgav, nullptr, nullptr, nullptr, 0, 0.f);
    sgemm128<0, false><<<gConv, blk>>>(Wgah, 0, x, sX, gah, sF, MD, NN, CC, bgah, nullptr, nullptr, nullptr, 0, 0.f);

    // Pass ah -> o_h (first half of out)
    sgemm128<3, true ><<<gScore, blk>>>(fh, sF, fa, sF, Am, sAm, NN, NN, MD, nullptr, nullptr, nullptr, nullptr, 0, alpha);
    softmax_rows<<<BB * NN, blk>>>(Am);
    sgemm128<4, false><<<gApply, blk>>>(gah, sF, Am, sAm, om, sF, MD, NN, NN, nullptr, nullptr, nullptr, nullptr, 0, 0.f);
    sgemm128<2, false><<<gOut,   blk>>>(Wfah, 0, om, sF, out, sX, CC, NN, MD, bfah, nullptr, nullptr, x, sX, 0.f);

    // Pass av -> o_v (second half of out)
    sgemm128<3, true ><<<gScore, blk>>>(fv, sF, fa, sF, Am, sAm, NN, NN, MD, nullptr, nullptr, nullptr, nullptr, 0, alpha);
    softmax_rows<<<BB * NN, blk>>>(Am);
    sgemm128<4, false><<<gApply, blk>>>(gav, sF, Am, sAm, om, sF, MD, NN, NN, nullptr, nullptr, nullptr, nullptr, 0, 0.f);
    sgemm128<2, false><<<gOut,   blk>>>(Wfav, 0, om, sF, out + halfOut, sX, CC, NN, MD, bfav, nullptr, nullptr, x, sX, 0.f);
}

// round 7
// speedup vs baseline: 1.1588x; 1.1588x over previous
#include <cuda_runtime.h>
#include <cuda_bf16.h>
#include <cstdint>
#include <cstddef>

#define BB 8
#define CC 512
#define NN 2304
#define MD 128
#define K3F 384     // 3*MD  packed K for score operands (hi|?|?)
#define K3N 6912    // 3*NN  packed K for apply operands

typedef __nv_bfloat16 bf16;

// ---- scratch (~505 MB static __device__) ----------------------------------
static __device__ float d_S  [(size_t)BB * NN * NN];    // 170 MB
static __device__ bf16  d_AT [(size_t)BB * NN * K3N];   // 255 MB
static __device__ bf16  d_faT[(size_t)BB * NN * K3F];
static __device__ bf16  d_fvT[(size_t)BB * NN * K3F];
static __device__ bf16  d_fhT[(size_t)BB * NN * K3F];
static __device__ bf16  d_gav[(size_t)BB * MD * K3N];
static __device__ bf16  d_gah[(size_t)BB * MD * K3N];
static __device__ float d_om [(size_t)BB * MD * NN];
static __device__ float d_mx [BB * NN];
static __device__ float d_inv[BB * NN];

__device__ __forceinline__ uint32_t smem_u32(const void* p) {
    uint32_t a;
    asm("{ .reg .u64 t; cvta.to.shared.u64 t, %1; cvt.u32.u64 %0, t; }" : "=r"(a) : "l"(p));
    return a;
}

// ---------------------------------------------------------------------------
// HMMA bf16 GEMM: D[128x128 tile] = alpha * A * B^T
//   A: [M, K2] bf16, K-contig, ld=ldA ; B: [N, K2] bf16, K-contig, ld=ldB
//   Out fp32 [.., ldO].  K2 % 64 == 0.
// 256 thr = 8 warps (2x4), warp tile 64x32, m16n8k16.row.col bf16->f32,
// cp.async double-buffered 128x64 smem tiles with SW128 swizzle.
// ---------------------------------------------------------------------------
__device__ __forceinline__ void tile_ld(uint32_t sdst, const bf16* __restrict__ g,
                                        int ld, int tid) {
#pragma unroll
    for (int it = 0; it < 4; ++it) {
        int s = tid + it * 256;
        int r = s >> 3, c = s & 7;               // 128 rows x 8 chunks of 16B
        uint32_t o = (uint32_t)(r * 128 + c * 16);
        o ^= (o >> 3) & 0x70;                    // SW128 swizzle
        asm volatile("cp.async.cg.shared.global [%0], [%1], 16;"
                     :: "r"(sdst + o), "l"(g + (size_t)r * ld + c * 8) : "memory");
    }
}

__global__ void __launch_bounds__(256, 1)
hmma_gemm(const bf16* __restrict__ A, size_t sA, int ldA,
          const bf16* __restrict__ B, size_t sB, int ldB,
          float* __restrict__ Out, size_t sO, int ldO,
          int K2, float alpha)
{
    extern __shared__ char smem[];
    const uint32_t sb = smem_u32(smem);
    const int tid = threadIdx.x, wid = tid >> 5, lane = tid & 31;
    const int b = blockIdx.z;
    const int i0 = blockIdx.y * 128, j0 = blockIdx.x * 128;
    A += (size_t)b * sA + (size_t)i0 * ldA;
    B += (size_t)b * sB + (size_t)j0 * ldB;
    Out += (size_t)b * sO;

    const int mW = (wid & 1) * 64;      // warp row origin
    const int nW = (wid >> 1) * 32;     // warp col origin

    float acc[4][4][4];
#pragma unroll
    for (int i = 0; i < 4; ++i)
#pragma unroll
        for (int j = 0; j < 4; ++j)
#pragma unroll
            for (int k = 0; k < 4; ++k) acc[i][j][k] = 0.f;

    const uint32_t oA[2] = { sb,         sb + 32768 };
    const uint32_t oB[2] = { sb + 16384, sb + 49152 };

    tile_ld(oA[0], A, ldA, tid);
    tile_ld(oB[0], B, ldB, tid);
    asm volatile("cp.async.commit_group;" ::: "memory");

    const int nC = K2 >> 6;
    const int li8 = lane & 7, sel = lane >> 3;
    int buf = 0;

    for (int c = 0; c < nC; ++c) {
        if (c + 1 < nC) {
            tile_ld(oA[buf ^ 1], A + (size_t)(c + 1) * 64, ldA, tid);
            tile_ld(oB[buf ^ 1], B + (size_t)(c + 1) * 64, ldB, tid);
            asm volatile("cp.async.commit_group;" ::: "memory");
            asm volatile("cp.async.wait_group 1;" ::: "memory");
        } else {
            asm volatile("cp.async.wait_group 0;" ::: "memory");
        }
        __syncthreads();

        const uint32_t ab = oA[buf], bb = oB[buf];
#pragma unroll
        for (int ks = 0; ks < 4; ++ks) {
            const int kb = ks * 32;                 // byte offset within 128B row
            uint32_t af[4][4], bfr[2][4];
#pragma unroll
            for (int mi = 0; mi < 4; ++mi) {
                int row = mW + mi * 16 + li8 + (sel & 1) * 8;
                uint32_t o = (uint32_t)(row * 128 + kb + (sel >> 1) * 16);
                o ^= (o >> 3) & 0x70;
                asm volatile("ldmatrix.sync.aligned.m8n8.x4.shared.b16 {%0,%1,%2,%3}, [%4];"
                    : "=r"(af[mi][0]), "=r"(af[mi][1]), "=r"(af[mi][2]), "=r"(af[mi][3])
                    : "r"(ab + o));
            }
#pragma unroll
            for (int nq = 0; nq < 2; ++nq) {
                int row = nW + nq * 16 + li8 + (sel >> 1) * 8;
                uint32_t o = (uint32_t)(row * 128 + kb + (sel & 1) * 16);
                o ^= (o >> 3) & 0x70;
                asm volatile("ldmatrix.sync.aligned.m8n8.x4.shared.b16 {%0,%1,%2,%3}, [%4];"
                    : "=r"(bfr[nq][0]), "=r"(bfr[nq][1]), "=r"(bfr[nq][2]), "=r"(bfr[nq][3])
                    : "r"(bb + o));
            }
#pragma unroll
            for (int mi = 0; mi < 4; ++mi)
#pragma unroll
                for (int ni = 0; ni < 4; ++ni) {
                    const uint32_t b0 = bfr[ni >> 1][(ni & 1) * 2];
                    const uint32_t b1 = bfr[ni >> 1][(ni & 1) * 2 + 1];
                    asm volatile(
                        "mma.sync.aligned.m16n8k16.row.col.f32.bf16.bf16.f32 "
                        "{%0,%1,%2,%3}, {%4,%5,%6,%7}, {%8,%9}, {%0,%1,%2,%3};"
                        : "+f"(acc[mi][ni][0]), "+f"(acc[mi][ni][1]),
                          "+f"(acc[mi][ni][2]), "+f"(acc[mi][ni][3])
                        : "r"(af[mi][0]), "r"(af[mi][1]), "r"(af[mi][2]), "r"(af[mi][3]),
                          "r"(b0), "r"(b1));
                }
        }
        __syncthreads();
        buf ^= 1;
    }

    const int g8 = lane >> 2, tg = lane & 3;
#pragma unroll
    for (int mi = 0; mi < 4; ++mi)
#pragma unroll
        for (int ni = 0; ni < 4; ++ni) {
            const int r  = i0 + mW + mi * 16 + g8;
            const int cN = j0 + nW + ni * 8 + tg * 2;
            float2 v0 = make_float2(acc[mi][ni][0] * alpha, acc[mi][ni][1] * alpha);
            float2 v1 = make_float2(acc[mi][ni][2] * alpha, acc[mi][ni][3] * alpha);
            *(float2*)&Out[(size_t)r * ldO + cN]       = v0;
            *(float2*)&Out[(size_t)(r + 8) * ldO + cN] = v1;
        }
}

// ---------------------------------------------------------------------------
// fp32 SIMT SGEMM (double-buffered, 128x128x16, 8x8 microtile).
// MODE 5: BN-ReLU -> packed bf16 fT[n, K3F]; PAT 0: (hi,hi,lo)  PAT 1: (hi,lo,hi)
// MODE 6: +bias   -> packed bf16 g [m, K3N]  (PAT 0 order)
// MODE 2: +bias + resid -> fp32 C[m, NN]  (B is [K, N] slab)
// ---------------------------------------------------------------------------
__device__ __forceinline__ void ld_tr(const float* __restrict__ P, int ld,
                                      int r0, int k0, int tid, float4& a, float4& b) {
    int s = tid;
    a = *(const float4*)&P[(size_t)(r0 + (s >> 2)) * ld + k0 + ((s & 3) << 2)];
    s = tid + 256;
    b = *(const float4*)&P[(size_t)(r0 + (s >> 2)) * ld + k0 + ((s & 3) << 2)];
}
__device__ __forceinline__ void ld_sl(const float* __restrict__ P, int ld,
                                      int n0, int k0, int tid, float4& a, float4& b) {
    int s = tid;
    a = *(const float4*)&P[(size_t)(k0 + (s >> 5)) * ld + n0 + ((s & 31) << 2)];
    s = tid + 256;
    b = *(const float4*)&P[(size_t)(k0 + (s >> 5)) * ld + n0 + ((s & 31) << 2)];
}
__device__ __forceinline__ void st_tr(float (*T)[128], int tid,
                                      const float4& a, const float4& b) {
    int s = tid, r = s >> 2, kq = (s & 3) << 2;
    T[kq + 0][r] = a.x; T[kq + 1][r] = a.y; T[kq + 2][r] = a.z; T[kq + 3][r] = a.w;
    s = tid + 256; r = s >> 2; kq = (s & 3) << 2;
    T[kq + 0][r] = b.x; T[kq + 1][r] = b.y; T[kq + 2][r] = b.z; T[kq + 3][r] = b.w;
}
__device__ __forceinline__ void st_sl(float (*T)[128], int tid,
                                      const float4& a, const float4& b) {
    int s = tid;
    *(float4*)&T[s >> 5][(s & 31) << 2] = a;
    s = tid + 256;
    *(float4*)&T[s >> 5][(s & 31) << 2] = b;
}

template<int MODE, int PAT>
__global__ void __launch_bounds__(256)
sgemm_simt(const float* __restrict__ A,             // [M,K] batch-shared weights
           const float* __restrict__ Bm, size_t sB, // [K,N] slab per batch
           float* __restrict__ C, size_t sC,
           bf16* __restrict__ O, size_t sO,
           int M, int N, int K,
           const float* __restrict__ bias,
           const float* __restrict__ gam, const float* __restrict__ bet,
           const float* __restrict__ resid, size_t sR)
{
    __shared__ float As[2][16][128];
    __shared__ float Bs[2][16][128];

    const int b = blockIdx.z;
    Bm += (size_t)b * sB;
    if (MODE == 2) { C += (size_t)b * sC; resid += (size_t)b * sR; }
    else           { O += (size_t)b * sO; }

    const int m0 = blockIdx.y * 128;
    const int n0 = blockIdx.x * 128;
    const int tid = threadIdx.x;
    const int ty = tid >> 4, tx = tid & 15;

    float acc[8][8];
#pragma unroll
    for (int i = 0; i < 8; ++i)
#pragma unroll
        for (int j = 0; j < 8; ++j) acc[i][j] = 0.f;

    float4 a0, a1, b0, b1;
    int buf = 0;

    ld_tr(A, K, m0, 0, tid, a0, a1);
    ld_sl(Bm, N, n0, 0, tid, b0, b1);
    st_tr(As[0], tid, a0, a1);
    st_sl(Bs[0], tid, b0, b1);
    __syncthreads();

    for (int k0 = 0; k0 < K; k0 += 16) {
        const bool nx = (k0 + 16) < K;
        if (nx) {
            ld_tr(A, K, m0, k0 + 16, tid, a0, a1);
            ld_sl(Bm, N, n0, k0 + 16, tid, b0, b1);
        }
#pragma unroll
        for (int k = 0; k < 16; ++k) {
            float ra[8], rb[8];
#pragma unroll
            for (int i = 0; i < 8; ++i) ra[i] = As[buf][k][ty * 8 + i];
#pragma unroll
            for (int j = 0; j < 8; ++j) rb[j] = Bs[buf][k][tx * 8 + j];
#pragma unroll
            for (int i = 0; i < 8; ++i)
#pragma unroll
                for (int j = 0; j < 8; ++j)
                    acc[i][j] = fmaf(ra[i], rb[j], acc[i][j]);
        }
        if (nx) {
            st_tr(As[buf ^ 1], tid, a0, a1);
            st_sl(Bs[buf ^ 1], tid, b0, b1);
            __syncthreads();
            buf ^= 1;
        }
    }

#pragma unroll
    for (int i = 0; i < 8; ++i) {
        const int m = m0 + ty * 8 + i;
        float sc = 1.f, bs = bias[m];
        if (MODE == 5) {
            sc = gam[m] * rsqrtf(1.f + 1e-5f);
            bs = fmaf(bias[m], sc, bet[m]);
        }
#pragma unroll
        for (int j = 0; j < 8; ++j) {
            const int n = n0 + tx * 8 + j;
            float v = acc[i][j];
            if (MODE == 5) {
                v = fmaxf(fmaf(v, sc, bs), 0.f);
                bf16 h = __float2bfloat16(v);
                bf16 l = __float2bfloat16(v - __bfloat162float(h));
                size_t o = (size_t)n * K3F;
                O[o + m]       = h;
                O[o + 128 + m] = PAT ? l : h;
                O[o + 256 + m] = PAT ? h : l;
            } else if (MODE == 6) {
                v += bs;
                bf16 h = __float2bfloat16(v);
                bf16 l = __float2bfloat16(v - __bfloat162float(h));
                size_t o = (size_t)m * K3N;
                O[o + n]          = h;
                O[o + NN + n]     = h;
                O[o + 2 * NN + n] = l;
            } else {
                C[(size_t)m * NN + n] = v + bs + resid[(size_t)m * NN + n];
            }
        }
    }
}

// ---------------------------------------------------------------------------
// Row stats of S: max and 1/sum(exp(v-max)) per row of 2304 (= 9*256)
// ---------------------------------------------------------------------------
__global__ void __launch_bounds__(256)
stats_rows(const float* __restrict__ S, float* __restrict__ mx, float* __restrict__ inv)
{
    const float* p = S + (size_t)blockIdx.x * NN;
    const int t = threadIdx.x;
    float v[9];
    float m = -3.4e38f;
#pragma unroll
    for (int r = 0; r < 9; ++r) { v[r] = p[t + (r << 8)]; m = fmaxf(m, v[r]); }
    __shared__ float red[8];
#pragma unroll
    for (int o = 16; o > 0; o >>= 1) m = fmaxf(m, __shfl_xor_sync(0xffffffffu, m, o));
    if ((t & 31) == 0) red[t >> 5] = m;
    __syncthreads();
    float m2 = red[0];
#pragma unroll
    for (int w = 1; w < 8; ++w) m2 = fmaxf(m2, red[w]);
    float s = 0.f;
#pragma unroll
    for (int r = 0; r < 9; ++r) s += __expf(v[r] - m2);
#pragma unroll
    for (int o = 16; o > 0; o >>= 1) s += __shfl_xor_sync(0xffffffffu, s, o);
    __syncthreads();
    if ((t & 31) == 0) red[t >> 5] = s;
    __syncthreads();
    float s2 = 0.f;
#pragma unroll
    for (int w = 0; w < 8; ++w) s2 += red[w];
    if (t == 0) { mx[blockIdx.x] = m2; inv[blockIdx.x] = 1.f / s2; }
}

// ---------------------------------------------------------------------------
// Normalize + transpose + packed split: A[n,j]=exp(S-m)*inv -> AT[j, K3N] (hi,lo,hi)
// ---------------------------------------------------------------------------
__global__ void __launch_bounds__(256)
normT(const float* __restrict__ S, const float* __restrict__ mx,
      const float* __restrict__ inv, bf16* __restrict__ AT)
{
    extern __shared__ char smem[];
    float* sm_m = (float*)smem;
    float* sm_i = (float*)(smem + 512);
    float (*V)[129] = (float(*)[129])(smem + 1024);

    const int b = blockIdx.z;
    const int n0 = blockIdx.y * 128;
    const int j0 = blockIdx.x * 128;
    S  += (size_t)b * NN * NN;
    AT += (size_t)b * NN * K3N;
    mx += (size_t)b * NN;
    inv += (size_t)b * NN;
    const int tid = threadIdx.x;

    if (tid < 128) { sm_m[tid] = mx[n0 + tid]; sm_i[tid] = inv[n0 + tid]; }
    __syncthreads();
    for (int e = tid; e < 16384; e += 256) {
        int r = e >> 7, c = e & 127;
        V[r][c] = __expf(S[(size_t)(n0 + r) * NN + j0 + c] - sm_m[r]) * sm_i[r];
    }
    __syncthreads();
    for (int e = tid; e < 16384; e += 256) {
        int jj = e >> 7, nn = e & 127;
        float v = V[nn][jj];
        bf16 h = __float2bfloat16(v);
        bf16 l = __float2bfloat16(v - __bfloat162float(h));
        size_t o = (size_t)(j0 + jj) * K3N + n0 + nn;
        AT[o]          = h;
        AT[o + NN]     = l;
        AT[o + 2 * NN] = h;
    }
}

// ---------------------------------------------------------------------------

extern "C" void kernel_launch(void* const* d_in, const int* in_sizes, int n_in,
                              void* d_out, int out_size)
{
    const float* x    = (const float*)d_in[0];
    const float* x_h  = (const float*)d_in[1];
    const float* x_v  = (const float*)d_in[2];
    const float* Wa   = (const float*)d_in[3];
    const float* ba   = (const float*)d_in[4];
    const float* ga   = (const float*)d_in[5];
    const float* ta   = (const float*)d_in[6];
    const float* Wv   = (const float*)d_in[7];
    const float* bv   = (const float*)d_in[8];
    const float* gv   = (const float*)d_in[9];
    const float* tv   = (const float*)d_in[10];
    const float* Wgav = (const float*)d_in[11];
    const float* bgav = (const float*)d_in[12];
    const float* Wgah = (const float*)d_in[13];
    const float* bgah = (const float*)d_in[14];
    const float* Wfav = (const float*)d_in[15];
    const float* bfav = (const float*)d_in[16];
    const float* Wfah = (const float*)d_in[17];
    const float* bfah = (const float*)d_in[18];
    float* out = (float*)d_out;

    float *S, *om, *mx, *inv;
    bf16 *AT, *faT, *fvT, *fhT, *gav, *gah;
    cudaGetSymbolAddress((void**)&S,   d_S);
    cudaGetSymbolAddress((void**)&AT,  d_AT);
    cudaGetSymbolAddress((void**)&faT, d_faT);
    cudaGetSymbolAddress((void**)&fvT, d_fvT);
    cudaGetSymbolAddress((void**)&fhT, d_fhT);
    cudaGetSymbolAddress((void**)&gav, d_gav);
    cudaGetSymbolAddress((void**)&gah, d_gah);
    cudaGetSymbolAddress((void**)&om,  d_om);
    cudaGetSymbolAddress((void**)&mx,  d_mx);
    cudaGetSymbolAddress((void**)&inv, d_inv);

    const int SMEM_HMMA = 65536;
    const int SMEM_NT   = 1024 + 128 * 129 * 4;
    cudaFuncSetAttribute(hmma_gemm, cudaFuncAttributeMaxDynamicSharedMemorySize, SMEM_HMMA);
    cudaFuncSetAttribute(normT,     cudaFuncAttributeMaxDynamicSharedMemorySize, SMEM_NT);

    const size_t sX  = (size_t)CC * NN;
    const size_t sF  = (size_t)NN * K3F;    // fT per batch
    const size_t sG  = (size_t)MD * K3N;    // g per batch
    const size_t sAT = (size_t)NN * K3N;
    const size_t sS  = (size_t)NN * NN;
    const size_t sOm = (size_t)MD * NN;
    const size_t halfOut = (size_t)BB * CC * NN;
    const float alpha = 0.08838834764831845f;  // 128^-0.5

    dim3 blk(256);
    dim3 gConv (NN / 128, 1, BB);
    dim3 gScore(NN / 128, NN / 128, BB);
    dim3 gApply(NN / 128, 1, BB);
    dim3 gOut  (NN / 128, CC / 128, BB);
    dim3 gNT   (NN / 128, NN / 128, BB);

    // Phase 1: input convs (fp32 SIMT, packed-bf16 epilogues)
    sgemm_simt<5, 1><<<gConv, blk>>>(Wa, x,   sX, nullptr, 0, faT, sF, MD, NN, CC, ba,   ga, ta, nullptr, 0);
    sgemm_simt<5, 0><<<gConv, blk>>>(Wv, x_v, sX, nullptr, 0, fvT, sF, MD, NN, CC, bv,   gv, tv, nullptr, 0);
    sgemm_simt<5, 0><<<gConv, blk>>>(Wv, x_h, sX, nullptr, 0, fhT, sF, MD, NN, CC, bv,   gv, tv, nullptr, 0);
    sgemm_simt<6, 0><<<gConv, blk>>>(Wgav, x, sX, nullptr, 0, gav, sG, MD, NN, CC, bgav, nullptr, nullptr, nullptr, 0);
    sgemm_simt<6, 0><<<gConv, blk>>>(Wgah, x, sX, nullptr, 0, gah, sG, MD, NN, CC, bgah, nullptr, nullptr, nullptr, 0);

    // Pass ah -> o_h (first half of out)
    hmma_gemm<<<gScore, blk, SMEM_HMMA>>>(fhT, sF, K3F, faT, sF, K3F, S, sS, NN, K3F, alpha);
    stats_rows<<<BB * NN, blk>>>(S, mx, inv);
    normT<<<gNT, blk, SMEM_NT>>>(S, mx, inv, AT);
    hmma_gemm<<<gApply, blk, SMEM_HMMA>>>(gah, sG, K3N, AT, sAT, K3N, om, sOm, NN, K3N, 1.f);
    sgemm_simt<2, 0><<<gOut, blk>>>(Wfah, om, sOm, out, sX, nullptr, 0, CC, NN, MD, bfah, nullptr, nullptr, x, sX);

    // Pass av -> o_v (second half of out)
    hmma_gemm<<<gScore, blk, SMEM_HMMA>>>(fvT, sF, K3F, faT, sF, K3F, S, sS, NN, K3F, alpha);
    stats_rows<<<BB * NN, blk>>>(S, mx, inv);
    normT<<<gNT, blk, SMEM_NT>>>(S, mx, inv, AT);
    hmma_gemm<<<gApply, blk, SMEM_HMMA>>>(gav, sG, K3N, AT, sAT, K3N, om, sOm, NN, K3N, 1.f);
    sgemm_simt<2, 0><<<gOut, blk>>>(Wfav, om, sOm, out + halfOut, sX, nullptr, 0, CC, NN, MD, bfav, nullptr, nullptr, x, sX);
}

// round 9
// speedup vs baseline: 1.7652x; 1.5233x over previous
#include <cuda_runtime.h>
#include <cuda_bf16.h>
#include <cstdint>
#include <cstddef>

#define BB 8
#define CC 512
#define NN 2304
#define MD 128
#define K3F 384     // 3*MD packed K for score operands
#define NTILE 18    // NN / 128

typedef __nv_bfloat16 bf16;

// ---- scratch --------------------------------------------------------------
static __device__ float d_E  [(size_t)BB * NN * NN];    // exp(alpha*S) [b][j][n]
static __device__ float d_ps [(size_t)BB * NTILE * NN]; // partial col sums
static __device__ float d_inv[BB * NN];
static __device__ bf16  d_faT[(size_t)BB * NN * K3F];
static __device__ bf16  d_fvT[(size_t)BB * NN * K3F];
static __device__ bf16  d_fhT[(size_t)BB * NN * K3F];
static __device__ float d_gav[(size_t)BB * MD * NN];
static __device__ float d_gah[(size_t)BB * MD * NN];
static __device__ bf16  d_ghi[(size_t)BB * MD * NN];
static __device__ bf16  d_glo[(size_t)BB * MD * NN];
static __device__ float d_om [(size_t)BB * MD * NN];

__device__ __forceinline__ uint32_t smem_u32(const void* p) {
    uint32_t a;
    asm("{ .reg .u64 t; cvta.to.shared.u64 t, %1; cvt.u32.u64 %0, t; }" : "=r"(a) : "l"(p));
    return a;
}

// 128-row x 128-byte tile -> smem with SW128 swizzle (bf16 ld in elements)
__device__ __forceinline__ void tile_ld(uint32_t sdst, const bf16* __restrict__ g,
                                        int ld, int tid) {
#pragma unroll
    for (int it = 0; it < 4; ++it) {
        int s = tid + it * 256;
        int r = s >> 3, c = s & 7;
        uint32_t o = (uint32_t)(r * 128 + c * 16);
        o ^= (o >> 3) & 0x70;
        asm volatile("cp.async.cg.shared.global [%0], [%1], 16;"
                     :: "r"(sdst + o), "l"(g + (size_t)r * ld + c * 8) : "memory");
    }
}
// 128-row x 64-float tile -> fp32 staging (row stride 272B, no swizzle)
__device__ __forceinline__ void stage_ld(uint32_t sdst, const float* __restrict__ g,
                                         int tid) {
#pragma unroll
    for (int it = 0; it < 8; ++it) {
        int s = tid + it * 256;
        int r = s >> 4, q = s & 15;
        asm volatile("cp.async.cg.shared.global [%0], [%1], 16;"
                     :: "r"(sdst + r * 272 + q * 16), "l"(g + (size_t)r * NN + q * 4)
                     : "memory");
    }
}
// split fp32 stage tile -> swizzled bf16 hi (at edst) / lo (at edst+16384)
__device__ __forceinline__ void cvt_tile(uint32_t sstage, uint32_t edst, int tid) {
    const int r = tid & 127, h = tid >> 7;
    const uint32_t src = sstage + r * 272 + h * 128;
#pragma unroll
    for (int i = 0; i < 8; ++i) {
        float4 v;
        asm volatile("ld.shared.v4.f32 {%0,%1,%2,%3}, [%4];"
                     : "=f"(v.x), "=f"(v.y), "=f"(v.z), "=f"(v.w) : "r"(src + i * 16));
        __nv_bfloat162 h01 = __floats2bfloat162_rn(v.x, v.y);
        __nv_bfloat162 h23 = __floats2bfloat162_rn(v.z, v.w);
        float2 f01 = __bfloat1622float2(h01);
        float2 f23 = __bfloat1622float2(h23);
        __nv_bfloat162 l01 = __floats2bfloat162_rn(v.x - f01.x, v.y - f01.y);
        __nv_bfloat162 l23 = __floats2bfloat162_rn(v.z - f23.x, v.w - f23.y);
        uint32_t o = (uint32_t)(r * 128 + h * 64 + i * 8);
        uint32_t sw = o ^ ((o >> 3) & 0x70);
        asm volatile("st.shared.v2.b32 [%0], {%1,%2};"
                     :: "r"(edst + sw), "r"(*(uint32_t*)&h01), "r"(*(uint32_t*)&h23)
                     : "memory");
        asm volatile("st.shared.v2.b32 [%0], {%1,%2};"
                     :: "r"(edst + 16384 + sw), "r"(*(uint32_t*)&l01), "r"(*(uint32_t*)&l23)
                     : "memory");
    }
}

#define LDSM4(d, a)                                                          \
    asm volatile("ldmatrix.sync.aligned.m8n8.x4.shared.b16 {%0,%1,%2,%3}, [%4];" \
        : "=r"((d)[0]), "=r"((d)[1]), "=r"((d)[2]), "=r"((d)[3]) : "r"(a))
#define MMA(ac, af, b0, b1)                                                  \
    asm volatile("mma.sync.aligned.m16n8k16.row.col.f32.bf16.bf16.f32 "      \
        "{%0,%1,%2,%3}, {%4,%5,%6,%7}, {%8,%9}, {%0,%1,%2,%3};"              \
        : "+f"((ac)[0]), "+f"((ac)[1]), "+f"((ac)[2]), "+f"((ac)[3])         \
        : "r"((af)[0]), "r"((af)[1]), "r"((af)[2]), "r"((af)[3]),            \
          "r"(b0), "r"(b1))

// ---------------------------------------------------------------------------
// Score: E[j,n] = exp(alpha * fqT[n,:].faT[j,:]) with packed 3-term K=384.
// Also writes per-tile column partial sums PS[b][ytile][n].
// ---------------------------------------------------------------------------
__global__ void __launch_bounds__(256, 1)
hmma_score(const bf16* __restrict__ A, const bf16* __restrict__ B, size_t sF,
           float* __restrict__ E, float* __restrict__ PS, float alpha)
{
    extern __shared__ char smem[];
    const uint32_t sb = smem_u32(smem);
    const int tid = threadIdx.x, wid = tid >> 5, lane = tid & 31;
    const int b = blockIdx.z;
    const int i0 = blockIdx.y * 128, j0 = blockIdx.x * 128;   // i0: j-rows, j0: n-cols
    A += (size_t)b * sF + (size_t)i0 * K3F;
    B += (size_t)b * sF + (size_t)j0 * K3F;
    E += (size_t)b * NN * NN;

    const int mW = (wid & 1) * 64, nW = (wid >> 1) * 32;
    float acc[4][4][4];
#pragma unroll
    for (int i = 0; i < 4; ++i)
#pragma unroll
        for (int j = 0; j < 4; ++j)
#pragma unroll
            for (int k = 0; k < 4; ++k) acc[i][j][k] = 0.f;

    const uint32_t oA[2] = { sb, sb + 32768 };
    const uint32_t oB[2] = { sb + 16384, sb + 49152 };
    tile_ld(oA[0], A, K3F, tid);
    tile_ld(oB[0], B, K3F, tid);
    asm volatile("cp.async.commit_group;" ::: "memory");

    const int li8 = lane & 7, sel = lane >> 3;
    int buf = 0;
    for (int c = 0; c < 6; ++c) {
        if (c + 1 < 6) {
            tile_ld(oA[buf ^ 1], A + (size_t)(c + 1) * 64, K3F, tid);
            tile_ld(oB[buf ^ 1], B + (size_t)(c + 1) * 64, K3F, tid);
            asm volatile("cp.async.commit_group;" ::: "memory");
            asm volatile("cp.async.wait_group 1;" ::: "memory");
        } else {
            asm volatile("cp.async.wait_group 0;" ::: "memory");
        }
        __syncthreads();
        const uint32_t ab = oA[buf], bb = oB[buf];
#pragma unroll
        for (int ks = 0; ks < 4; ++ks) {
            const int kb = ks * 32;
            uint32_t af[4][4], bfr[2][4];
#pragma unroll
            for (int mi = 0; mi < 4; ++mi) {
                int row = mW + mi * 16 + li8 + (sel & 1) * 8;
                uint32_t o = (uint32_t)(row * 128 + kb + (sel >> 1) * 16);
                o ^= (o >> 3) & 0x70;
                LDSM4(af[mi], ab + o);
            }
#pragma unroll
            for (int nq = 0; nq < 2; ++nq) {
                int row = nW + nq * 16 + li8 + (sel >> 1) * 8;
                uint32_t o = (uint32_t)(row * 128 + kb + (sel & 1) * 16);
                o ^= (o >> 3) & 0x70;
                LDSM4(bfr[nq], bb + o);
            }
#pragma unroll
            for (int mi = 0; mi < 4; ++mi)
#pragma unroll
                for (int ni = 0; ni < 4; ++ni)
                    MMA(acc[mi][ni], af[mi],
                        bfr[ni >> 1][(ni & 1) * 2], bfr[ni >> 1][(ni & 1) * 2 + 1]);
        }
        __syncthreads();
        buf ^= 1;
    }

    // epilogue: exp + store E + column partial sums
    const int g8 = lane >> 2, tg = lane & 3;
    float ev[4][4][4];
#pragma unroll
    for (int mi = 0; mi < 4; ++mi)
#pragma unroll
        for (int ni = 0; ni < 4; ++ni)
#pragma unroll
            for (int k = 0; k < 4; ++k)
                ev[mi][ni][k] = __expf(acc[mi][ni][k] * alpha);
#pragma unroll
    for (int mi = 0; mi < 4; ++mi)
#pragma unroll
        for (int ni = 0; ni < 4; ++ni) {
            const int r  = i0 + mW + mi * 16 + g8;
            const int cN = j0 + nW + ni * 8 + tg * 2;
            *(float2*)&E[(size_t)r * NN + cN]       = make_float2(ev[mi][ni][0], ev[mi][ni][1]);
            *(float2*)&E[(size_t)(r + 8) * NN + cN] = make_float2(ev[mi][ni][2], ev[mi][ni][3]);
        }
    float cs[8];
#pragma unroll
    for (int ni = 0; ni < 4; ++ni)
#pragma unroll
        for (int par = 0; par < 2; ++par) {
            float s = 0.f;
#pragma unroll
            for (int mi = 0; mi < 4; ++mi)
                s += ev[mi][ni][par] + ev[mi][ni][2 + par];
            cs[ni * 2 + par] = s;
        }
#pragma unroll
    for (int o = 4; o <= 16; o <<= 1)
#pragma unroll
        for (int e = 0; e < 8; ++e)
            cs[e] += __shfl_xor_sync(0xffffffffu, cs[e], o);
    float* sP = (float*)smem;     // [2][128] (reuse tile smem)
    if (g8 == 0) {
#pragma unroll
        for (int ni = 0; ni < 4; ++ni)
#pragma unroll
            for (int par = 0; par < 2; ++par)
                sP[(wid & 1) * 128 + nW + ni * 8 + tg * 2 + par] = cs[ni * 2 + par];
    }
    __syncthreads();
    if (tid < 128)
        PS[((size_t)(b * NTILE + blockIdx.y)) * NN + j0 + tid] = sP[tid] + sP[128 + tid];
}

// ---------------------------------------------------------------------------
// inv[b][n] = 1 / sum_t PS[b][t][n]
__global__ void __launch_bounds__(256)
finalize_inv(const float* __restrict__ PS, float* __restrict__ inv)
{
    const int b = blockIdx.z;
    const int n = blockIdx.x * 256 + threadIdx.x;
    float s = 0.f;
#pragma unroll
    for (int t = 0; t < NTILE; ++t)
        s += PS[((size_t)(b * NTILE + t)) * NN + n];
    inv[b * NN + n] = 1.f / s;
}

// ghi/glo[b][m][n] = split(g[b][m][n] * inv[b][n])
__global__ void __launch_bounds__(128)
gsplit(const float* __restrict__ g, const float* __restrict__ inv,
       bf16* __restrict__ Ghi, bf16* __restrict__ Glo)
{
    const int b = blockIdx.z, m = blockIdx.y;
    const int n = blockIdx.x * 128 + threadIdx.x;
    const size_t idx = ((size_t)b * MD + m) * NN + n;
    float v = g[idx] * inv[b * NN + n];
    bf16 h = __float2bfloat16(v);
    Ghi[idx] = h;
    Glo[idx] = __float2bfloat16(v - __bfloat162float(h));
}

// ---------------------------------------------------------------------------
// Fused apply: om[m,j] = sum_n g'[m,n] * E[j,n]  (3-term bf16 split, K=2304)
// A tiles (g' hi/lo) via cp.async of pre-packed bf16; B tiles (E hi/lo)
// generated in-kernel from fp32 E staged via cp.async.
// ---------------------------------------------------------------------------
__global__ void __launch_bounds__(256, 1)
apply_fused(const bf16* __restrict__ Ghi, const bf16* __restrict__ Glo,
            const float* __restrict__ E, float* __restrict__ Om)
{
    extern __shared__ char smem[];
    const uint32_t sb = smem_u32(smem);
    const int tid = threadIdx.x, wid = tid >> 5, lane = tid & 31;
    const int b = blockIdx.z;
    const int j0 = blockIdx.x * 128;
    Ghi += (size_t)b * MD * NN;
    Glo += (size_t)b * MD * NN;
    E   += (size_t)b * NN * NN + (size_t)j0 * NN;
    Om  += (size_t)b * MD * NN;

    const uint32_t A0 = 0, A1 = 32768, E0 = 65536, E1 = 98304,
                   S0 = 131072, S1 = 165888;
    const int mW = (wid & 1) * 64, nW = (wid >> 1) * 32;

    float acc[4][4][4];
#pragma unroll
    for (int i = 0; i < 4; ++i)
#pragma unroll
        for (int j = 0; j < 4; ++j)
#pragma unroll
            for (int k = 0; k < 4; ++k) acc[i][j][k] = 0.f;

    // prologue
    tile_ld(sb + A0,         Ghi, NN, tid);
    tile_ld(sb + A0 + 16384, Glo, NN, tid);
    stage_ld(sb + S0, E, tid);
    asm volatile("cp.async.commit_group;" ::: "memory");
    asm volatile("cp.async.wait_group 0;" ::: "memory");
    __syncthreads();
    cvt_tile(sb + S0, sb + E0, tid);
    tile_ld(sb + A1,         Ghi + 64, NN, tid);
    tile_ld(sb + A1 + 16384, Glo + 64, NN, tid);
    stage_ld(sb + S1, E + 64, tid);
    asm volatile("cp.async.commit_group;" ::: "memory");
    __syncthreads();

    const int li8 = lane & 7, sel = lane >> 3;
    for (int c = 0; c < 36; ++c) {
        const uint32_t Ab = (c & 1) ? A1 : A0;
        const uint32_t Eb = (c & 1) ? E1 : E0;
#pragma unroll
        for (int ks = 0; ks < 4; ++ks) {
            const int kb = ks * 32;
            uint32_t ah[4][4], al[4][4], bh[2][4], bl[2][4];
#pragma unroll
            for (int mi = 0; mi < 4; ++mi) {
                int row = mW + mi * 16 + li8 + (sel & 1) * 8;
                uint32_t o = (uint32_t)(row * 128 + kb + (sel >> 1) * 16);
                o ^= (o >> 3) & 0x70;
                LDSM4(ah[mi], Ab + sb + o);
                LDSM4(al[mi], Ab + sb + 16384 + o);
            }
#pragma unroll
            for (int nq = 0; nq < 2; ++nq) {
                int row = nW + nq * 16 + li8 + (sel >> 1) * 8;
                uint32_t o = (uint32_t)(row * 128 + kb + (sel & 1) * 16);
                o ^= (o >> 3) & 0x70;
                LDSM4(bh[nq], Eb + sb + o);
                LDSM4(bl[nq], Eb + sb + 16384 + o);
            }
#pragma unroll
            for (int mi = 0; mi < 4; ++mi)
#pragma unroll
                for (int ni = 0; ni < 4; ++ni) {
                    const int q = ni >> 1, p = (ni & 1) * 2;
                    MMA(acc[mi][ni], ah[mi], bh[q][p], bh[q][p + 1]);
                    MMA(acc[mi][ni], ah[mi], bl[q][p], bl[q][p + 1]);
                    MMA(acc[mi][ni], al[mi], bh[q][p], bh[q][p + 1]);
                }
        }
        if (c + 1 < 36) {
            asm volatile("cp.async.wait_group 0;" ::: "memory");
            __syncthreads();
            const uint32_t Sq = (c & 1) ? S0 : S1;
            const uint32_t Eq = (c & 1) ? E0 : E1;
            cvt_tile(sb + Sq, sb + Eq, tid);
            if (c + 2 < 36) {
                const uint32_t Ap = (c & 1) ? A1 : A0;
                const uint32_t Sp = (c & 1) ? S1 : S0;
                tile_ld(sb + Ap,         Ghi + (size_t)(c + 2) * 64, NN, tid);
                tile_ld(sb + Ap + 16384, Glo + (size_t)(c + 2) * 64, NN, tid);
                stage_ld(sb + Sp, E + (size_t)(c + 2) * 64, tid);
                asm volatile("cp.async.commit_group;" ::: "memory");
            }
            __syncthreads();
        }
    }

    const int g8 = lane >> 2, tg = lane & 3;
#pragma unroll
    for (int mi = 0; mi < 4; ++mi)
#pragma unroll
        for (int ni = 0; ni < 4; ++ni) {
            const int r  = mW + mi * 16 + g8;
            const int cN = j0 + nW + ni * 8 + tg * 2;
            *(float2*)&Om[(size_t)r * NN + cN]       = make_float2(acc[mi][ni][0], acc[mi][ni][1]);
            *(float2*)&Om[(size_t)(r + 8) * NN + cN] = make_float2(acc[mi][ni][2], acc[mi][ni][3]);
        }
}

// ---------------------------------------------------------------------------
// fp32 SIMT SGEMM (double-buffered, 128x128x16, 8x8 microtile).
// MODE 5: BN-ReLU -> packed bf16 fT[n,K3F]; PAT0 (hi,hi,lo), PAT1 (hi,lo,hi)
// MODE 0: +bias -> fp32 C[m,NN]
// MODE 2: +bias + resid -> fp32 C[m,NN]
// ---------------------------------------------------------------------------
__device__ __forceinline__ void ld_tr(const float* __restrict__ P, int ld,
                                      int r0, int k0, int tid, float4& a, float4& b) {
    int s = tid;
    a = *(const float4*)&P[(size_t)(r0 + (s >> 2)) * ld + k0 + ((s & 3) << 2)];
    s = tid + 256;
    b = *(const float4*)&P[(size_t)(r0 + (s >> 2)) * ld + k0 + ((s & 3) << 2)];
}
__device__ __forceinline__ void ld_sl(const float* __restrict__ P, int ld,
                                      int n0, int k0, int tid, float4& a, float4& b) {
    int s = tid;
    a = *(const float4*)&P[(size_t)(k0 + (s >> 5)) * ld + n0 + ((s & 31) << 2)];
    s = tid + 256;
    b = *(const float4*)&P[(size_t)(k0 + (s >> 5)) * ld + n0 + ((s & 31) << 2)];
}
__device__ __forceinline__ void st_tr(float (*T)[128], int tid,
                                      const float4& a, const float4& b) {
    int s = tid, r = s >> 2, kq = (s & 3) << 2;
    T[kq + 0][r] = a.x; T[kq + 1][r] = a.y; T[kq + 2][r] = a.z; T[kq + 3][r] = a.w;
    s = tid + 256; r = s >> 2; kq = (s & 3) << 2;
    T[kq + 0][r] = b.x; T[kq + 1][r] = b.y; T[kq + 2][r] = b.z; T[kq + 3][r] = b.w;
}
__device__ __forceinline__ void st_sl(float (*T)[128], int tid,
                                      const float4& a, const float4& b) {
    int s = tid;
    *(float4*)&T[s >> 5][(s & 31) << 2] = a;
    s = tid + 256;
    *(float4*)&T[s >> 5][(s & 31) << 2] = b;
}

template<int MODE, int PAT>
__global__ void __launch_bounds__(256)
sgemm_simt(const float* __restrict__ A,
           const float* __restrict__ Bm, size_t sB,
           float* __restrict__ C, size_t sC,
           bf16* __restrict__ O, size_t sO,
           int M, int N, int K,
           const float* __restrict__ bias,
           const float* __restrict__ gam, const float* __restrict__ bet,
           const float* __restrict__ resid, size_t sR)
{
    __shared__ float As[2][16][128];
    __shared__ float Bs[2][16][128];

    const int b = blockIdx.z;
    Bm += (size_t)b * sB;
    if (MODE == 5) O += (size_t)b * sO;
    else           C += (size_t)b * sC;
    if (MODE == 2) resid += (size_t)b * sR;

    const int m0 = blockIdx.y * 128;
    const int n0 = blockIdx.x * 128;
    const int tid = threadIdx.x;
    const int ty = tid >> 4, tx = tid & 15;

    float acc[8][8];
#pragma unroll
    for (int i = 0; i < 8; ++i)
#pragma unroll
        for (int j = 0; j < 8; ++j) acc[i][j] = 0.f;

    float4 a0, a1, b0, b1;
    int buf = 0;
    ld_tr(A, K, m0, 0, tid, a0, a1);
    ld_sl(Bm, N, n0, 0, tid, b0, b1);
    st_tr(As[0], tid, a0, a1);
    st_sl(Bs[0], tid, b0, b1);
    __syncthreads();

    for (int k0 = 0; k0 < K; k0 += 16) {
        const bool nx = (k0 + 16) < K;
        if (nx) {
            ld_tr(A, K, m0, k0 + 16, tid, a0, a1);
            ld_sl(Bm, N, n0, k0 + 16, tid, b0, b1);
        }
#pragma unroll
        for (int k = 0; k < 16; ++k) {
            float ra[8], rb[8];
#pragma unroll
            for (int i = 0; i < 8; ++i) ra[i] = As[buf][k][ty * 8 + i];
#pragma unroll
            for (int j = 0; j < 8; ++j) rb[j] = Bs[buf][k][tx * 8 + j];
#pragma unroll
            for (int i = 0; i < 8; ++i)
#pragma unroll
                for (int j = 0; j < 8; ++j)
                    acc[i][j] = fmaf(ra[i], rb[j], acc[i][j]);
        }
        if (nx) {
            st_tr(As[buf ^ 1], tid, a0, a1);
            st_sl(Bs[buf ^ 1], tid, b0, b1);
            __syncthreads();
            buf ^= 1;
        }
    }

#pragma unroll
    for (int i = 0; i < 8; ++i) {
        const int m = m0 + ty * 8 + i;
        float sc = 1.f, bs = bias[m];
        if (MODE == 5) {
            sc = gam[m] * rsqrtf(1.f + 1e-5f);
            bs = fmaf(bias[m], sc, bet[m]);
        }
#pragma unroll
        for (int j = 0; j < 8; ++j) {
            const int n = n0 + tx * 8 + j;
            float v = acc[i][j];
            if (MODE == 5) {
                v = fmaxf(fmaf(v, sc, bs), 0.f);
                bf16 h = __float2bfloat16(v);
                bf16 l = __float2bfloat16(v - __bfloat162float(h));
                size_t o = (size_t)n * K3F;
                O[o + m]       = h;
                O[o + 128 + m] = PAT ? l : h;
                O[o + 256 + m] = PAT ? h : l;
            } else if (MODE == 0) {
                C[(size_t)m * NN + n] = v + bs;
            } else {
                C[(size_t)m * NN + n] = v + bs + resid[(size_t)m * NN + n];
            }
        }
    }
}

// ---------------------------------------------------------------------------

extern "C" void kernel_launch(void* const* d_in, const int* in_sizes, int n_in,
                              void* d_out, int out_size)
{
    const float* x    = (const float*)d_in[0];
    const float* x_h  = (const float*)d_in[1];
    const float* x_v  = (const float*)d_in[2];
    const float* Wa   = (const float*)d_in[3];
    const float* ba   = (const float*)d_in[4];
    const float* ga   = (const float*)d_in[5];
    const float* ta   = (const float*)d_in[6];
    const float* Wv   = (const float*)d_in[7];
    const float* bv   = (const float*)d_in[8];
    const float* gv   = (const float*)d_in[9];
    const float* tv   = (const float*)d_in[10];
    const float* Wgav = (const float*)d_in[11];
    const float* bgav = (const float*)d_in[12];
    const float* Wgah = (const float*)d_in[13];
    const float* bgah = (const float*)d_in[14];
    const float* Wfav = (const float*)d_in[15];
    const float* bfav = (const float*)d_in[16];
    const float* Wfah = (const float*)d_in[17];
    const float* bfah = (const float*)d_in[18];
    float* out = (float*)d_out;

    float *E, *ps, *inv, *gav, *gah, *om;
    bf16 *faT, *fvT, *fhT, *ghi, *glo;
    cudaGetSymbolAddress((void**)&E,   d_E);
    cudaGetSymbolAddress((void**)&ps,  d_ps);
    cudaGetSymbolAddress((void**)&inv, d_inv);
    cudaGetSymbolAddress((void**)&faT, d_faT);
    cudaGetSymbolAddress((void**)&fvT, d_fvT);
    cudaGetSymbolAddress((void**)&fhT, d_fhT);
    cudaGetSymbolAddress((void**)&gav, d_gav);
    cudaGetSymbolAddress((void**)&gah, d_gah);
    cudaGetSymbolAddress((void**)&ghi, d_ghi);
    cudaGetSymbolAddress((void**)&glo, d_glo);
    cudaGetSymbolAddress((void**)&om,  d_om);

    const int SMEM_SC = 65536;
    const int SMEM_AP = 200704;
    cudaFuncSetAttribute(hmma_score,  cudaFuncAttributeMaxDynamicSharedMemorySize, SMEM_SC);
    cudaFuncSetAttribute(apply_fused, cudaFuncAttributeMaxDynamicSharedMemorySize, SMEM_AP);

    const size_t sX  = (size_t)CC * NN;
    const size_t sF  = (size_t)NN * K3F;
    const size_t sG  = (size_t)MD * NN;
    const size_t halfOut = (size_t)BB * CC * NN;
    const float alpha = 0.08838834764831845f;  // 128^-0.5

    dim3 blk(256);
    dim3 gConv (NN / 128, 1, BB);
    dim3 gScore(NN / 128, NN / 128, BB);
    dim3 gApply(NN / 128, 1, BB);
    dim3 gOut  (NN / 128, CC / 128, BB);
    dim3 gInv  (NN / 256, 1, BB);
    dim3 gGs   (NN / 128, MD, BB);

    // Phase 1: input convs
    sgemm_simt<5, 1><<<gConv, blk>>>(Wa, x,   sX, nullptr, 0, faT, sF, MD, NN, CC, ba,   ga, ta, nullptr, 0);
    sgemm_simt<5, 0><<<gConv, blk>>>(Wv, x_v, sX, nullptr, 0, fvT, sF, MD, NN, CC, bv,   gv, tv, nullptr, 0);
    sgemm_simt<5, 0><<<gConv, blk>>>(Wv, x_h, sX, nullptr, 0, fhT, sF, MD, NN, CC, bv,   gv, tv, nullptr, 0);
    sgemm_simt<0, 0><<<gConv, blk>>>(Wgav, x, sX, gav, sG, nullptr, 0, MD, NN, CC, bgav, nullptr, nullptr, nullptr, 0);
    sgemm_simt<0, 0><<<gConv, blk>>>(Wgah, x, sX, gah, sG, nullptr, 0, MD, NN, CC, bgah, nullptr, nullptr, nullptr, 0);

    // Pass ah -> o_h
    hmma_score<<<gScore, blk, SMEM_SC>>>(faT, fhT, sF, E, ps, alpha);
    finalize_inv<<<gInv, blk>>>(ps, inv);
    gsplit<<<gGs, 128>>>(gah, inv, ghi, glo);
    apply_fused<<<gApply, blk, SMEM_AP>>>(ghi, glo, E, om);
    sgemm_simt<2, 0><<<gOut, blk>>>(Wfah, om, sG, out, sX, nullptr, 0, CC, NN, MD, bfah, nullptr, nullptr, x, sX);

    // Pass av -> o_v
    hmma_score<<<gScore, blk, SMEM_SC>>>(faT, fvT, sF, E, ps, alpha);
    finalize_inv<<<gInv, blk>>>(ps, inv);
    gsplit<<<gGs, 128>>>(gav, inv, ghi, glo);
    apply_fused<<<gApply, blk, SMEM_AP>>>(ghi, glo, E, om);
    sgemm_simt<2, 0><<<gOut, blk>>>(Wfav, om, sG, out + halfOut, sX, nullptr, 0, CC, NN, MD, bfav, nullptr, nullptr, x, sX);
}

// round 10
// speedup vs baseline: 2.4147x; 1.3679x over previous
#include <cuda_runtime.h>
#include <cuda_bf16.h>
#include <cstdint>
#include <cstddef>

#define BB 8
#define CC 512
#define NN 2304
#define MD 128
#define K3F 384     // 3*MD  packed K (score operands, out-conv K)
#define K3C 1536    // 3*CC  packed K (input conv K)
#define NTILE 18    // NN / 128

typedef __nv_bfloat16 bf16;

// ---- scratch --------------------------------------------------------------
static __device__ float d_E   [(size_t)BB * NN * NN];    // exp(alpha*S) [b][j][n]
static __device__ float d_ps  [(size_t)BB * NTILE * NN];
static __device__ float d_inv [BB * NN];
static __device__ bf16  d_xT  [(size_t)BB * NN * K3C];   // x^T packed (hi,hi,lo)
static __device__ bf16  d_xvT [(size_t)BB * NN * K3C];
static __device__ bf16  d_xhT [(size_t)BB * NN * K3C];
static __device__ bf16  d_faT [(size_t)BB * NN * K3F];
static __device__ bf16  d_fvT [(size_t)BB * NN * K3F];
static __device__ bf16  d_fhT [(size_t)BB * NN * K3F];
static __device__ bf16  d_Wap  [MD * K3C];
static __device__ bf16  d_Wvp  [MD * K3C];
static __device__ bf16  d_Wgavp[MD * K3C];
static __device__ bf16  d_Wgahp[MD * K3C];
static __device__ bf16  d_Wfavp[CC * K3F];
static __device__ bf16  d_Wfahp[CC * K3F];
static __device__ bf16  d_gavhi[(size_t)BB * MD * NN], d_gavlo[(size_t)BB * MD * NN];
static __device__ bf16  d_gahhi[(size_t)BB * MD * NN], d_gahlo[(size_t)BB * MD * NN];
static __device__ bf16  d_OmT [(size_t)BB * NN * K3F]; // om^T packed (hi,hi,lo)

__device__ __forceinline__ uint32_t smem_u32(const void* p) {
    uint32_t a;
    asm("{ .reg .u64 t; cvta.to.shared.u64 t, %1; cvt.u32.u64 %0, t; }" : "=r"(a) : "l"(p));
    return a;
}

// 128-row x 128-byte bf16 tile -> smem with SW128 swizzle
__device__ __forceinline__ void tile_ld(uint32_t sdst, const bf16* __restrict__ g,
                                        int ld, int tid) {
#pragma unroll
    for (int it = 0; it < 4; ++it) {
        int s = tid + it * 256;
        int r = s >> 3, c = s & 7;
        uint32_t o = (uint32_t)(r * 128 + c * 16);
        o ^= (o >> 3) & 0x70;
        asm volatile("cp.async.cg.shared.global [%0], [%1], 16;"
                     :: "r"(sdst + o), "l"(g + (size_t)r * ld + c * 8) : "memory");
    }
}
// 128-row x 64-float tile -> fp32 staging (row stride 272B)
__device__ __forceinline__ void stage_ld(uint32_t sdst, const float* __restrict__ g,
                                         int tid) {
#pragma unroll
    for (int it = 0; it < 8; ++it) {
        int s = tid + it * 256;
        int r = s >> 4, q = s & 15;
        asm volatile("cp.async.cg.shared.global [%0], [%1], 16;"
                     :: "r"(sdst + r * 272 + q * 16), "l"(g + (size_t)r * NN + q * 4)
                     : "memory");
    }
}
// split fp32 stage tile * inv[n] -> swizzled bf16 hi (edst) / lo (edst+16384)
__device__ __forceinline__ void cvt_tile(uint32_t sstage, uint32_t edst, int tid,
                                         const float* __restrict__ invp) {
    const int r = tid & 127, h = tid >> 7;
    const uint32_t src = sstage + r * 272 + h * 128;
#pragma unroll
    for (int i = 0; i < 8; ++i) {
        float4 v;
        asm volatile("ld.shared.v4.f32 {%0,%1,%2,%3}, [%4];"
                     : "=f"(v.x), "=f"(v.y), "=f"(v.z), "=f"(v.w) : "r"(src + i * 16));
        float4 iv = *(const float4*)(invp + h * 32 + i * 4);
        v.x *= iv.x; v.y *= iv.y; v.z *= iv.z; v.w *= iv.w;
        __nv_bfloat162 h01 = __floats2bfloat162_rn(v.x, v.y);
        __nv_bfloat162 h23 = __floats2bfloat162_rn(v.z, v.w);
        float2 f01 = __bfloat1622float2(h01);
        float2 f23 = __bfloat1622float2(h23);
        __nv_bfloat162 l01 = __floats2bfloat162_rn(v.x - f01.x, v.y - f01.y);
        __nv_bfloat162 l23 = __floats2bfloat162_rn(v.z - f23.x, v.w - f23.y);
        uint32_t o = (uint32_t)(r * 128 + h * 64 + i * 8);
        uint32_t sw = o ^ ((o >> 3) & 0x70);
        asm volatile("st.shared.v2.b32 [%0], {%1,%2};"
                     :: "r"(edst + sw), "r"(*(uint32_t*)&h01), "r"(*(uint32_t*)&h23)
                     : "memory");
        asm volatile("st.shared.v2.b32 [%0], {%1,%2};"
                     :: "r"(edst + 16384 + sw), "r"(*(uint32_t*)&l01), "r"(*(uint32_t*)&l23)
                     : "memory");
    }
}

#define LDSM4(d, a)                                                          \
    asm volatile("ldmatrix.sync.aligned.m8n8.x4.shared.b16 {%0,%1,%2,%3}, [%4];" \
        : "=r"((d)[0]), "=r"((d)[1]), "=r"((d)[2]), "=r"((d)[3]) : "r"(a))
#define MMA(ac, af, b0, b1)                                                  \
    asm volatile("mma.sync.aligned.m16n8k16.row.col.f32.bf16.bf16.f32 "      \
        "{%0,%1,%2,%3}, {%4,%5,%6,%7}, {%8,%9}, {%0,%1,%2,%3};"              \
        : "+f"((ac)[0]), "+f"((ac)[1]), "+f"((ac)[2]), "+f"((ac)[3])         \
        : "r"((af)[0]), "r"((af)[1]), "r"((af)[2]), "r"((af)[3]),            \
          "r"(b0), "r"(b1))

// ---------------------------------------------------------------------------
// Generic conv HMMA: acc[m,n] = Aw[m,:].Bx[n,:] over packed K3.
// EPI 0: BN-ReLU, write fT packed [n, K3F] (PAT0: hi,hi,lo / PAT1: hi,lo,hi)
// EPI 1: +bias, split -> Ghi/Glo bf16 [m, NN]
// EPI 2: +bias + resid -> fp32 C [m, NN]
// ---------------------------------------------------------------------------
template<int EPI, int PAT>
__global__ void __launch_bounds__(256, 1)
hmma_conv(const bf16* __restrict__ Aw,                 // [Ma, K3] batch-shared
          const bf16* __restrict__ Bx, size_t sB,      // [N, K3] per batch
          int K3,
          float* __restrict__ Cf, size_t sC,
          bf16* __restrict__ O1, bf16* __restrict__ O2, size_t sO,
          const float* __restrict__ bias,
          const float* __restrict__ gam, const float* __restrict__ bet,
          const float* __restrict__ resid, size_t sR)
{
    extern __shared__ char smem[];
    const uint32_t sb = smem_u32(smem);
    const int tid = threadIdx.x, wid = tid >> 5, lane = tid & 31;
    const int b = blockIdx.z;
    const int m0 = blockIdx.y * 128, n0 = blockIdx.x * 128;
    Aw += (size_t)m0 * K3;
    Bx += (size_t)b * sB + (size_t)n0 * K3;
    if (EPI == 2) { Cf += (size_t)b * sC; resid += (size_t)b * sR; }
    else if (EPI == 1) { O1 += (size_t)b * sO; O2 += (size_t)b * sO; }
    else { O1 += (size_t)b * sO; }

    const int mW = (wid & 1) * 64, nW = (wid >> 1) * 32;
    float acc[4][4][4];
#pragma unroll
    for (int i = 0; i < 4; ++i)
#pragma unroll
        for (int j = 0; j < 4; ++j)
#pragma unroll
            for (int k = 0; k < 4; ++k) acc[i][j][k] = 0.f;

    const uint32_t oA[2] = { sb, sb + 32768 };
    const uint32_t oB[2] = { sb + 16384, sb + 49152 };
    tile_ld(oA[0], Aw, K3, tid);
    tile_ld(oB[0], Bx, K3, tid);
    asm volatile("cp.async.commit_group;" ::: "memory");

    const int li8 = lane & 7, sel = lane >> 3;
    const int nC = K3 >> 6;
    int buf = 0;
    for (int c = 0; c < nC; ++c) {
        if (c + 1 < nC) {
            tile_ld(oA[buf ^ 1], Aw + (size_t)(c + 1) * 64, K3, tid);
            tile_ld(oB[buf ^ 1], Bx + (size_t)(c + 1) * 64, K3, tid);
            asm volatile("cp.async.commit_group;" ::: "memory");
            asm volatile("cp.async.wait_group 1;" ::: "memory");
        } else {
            asm volatile("cp.async.wait_group 0;" ::: "memory");
        }
        __syncthreads();
        const uint32_t ab = oA[buf], bb = oB[buf];
#pragma unroll
        for (int ks = 0; ks < 4; ++ks) {
            const int kb = ks * 32;
            uint32_t af[4][4], bfr[2][4];
#pragma unroll
            for (int mi = 0; mi < 4; ++mi) {
                int row = mW + mi * 16 + li8 + (sel & 1) * 8;
                uint32_t o = (uint32_t)(row * 128 + kb + (sel >> 1) * 16);
                o ^= (o >> 3) & 0x70;
                LDSM4(af[mi], ab + o);
            }
#pragma unroll
            for (int nq = 0; nq < 2; ++nq) {
                int row = nW + nq * 16 + li8 + (sel >> 1) * 8;
                uint32_t o = (uint32_t)(row * 128 + kb + (sel & 1) * 16);
                o ^= (o >> 3) & 0x70;
                LDSM4(bfr[nq], bb + o);
            }
#pragma unroll
            for (int mi = 0; mi < 4; ++mi)
#pragma unroll
                for (int ni = 0; ni < 4; ++ni)
                    MMA(acc[mi][ni], af[mi],
                        bfr[ni >> 1][(ni & 1) * 2], bfr[ni >> 1][(ni & 1) * 2 + 1]);
        }
        __syncthreads();
        buf ^= 1;
    }

    const int g8 = lane >> 2, tg = lane & 3;
    if (EPI == 0) {
        // BN-ReLU into stage[n_local][m], then packed split write
        float (*stage)[129] = (float(*)[129])smem;
        const float rs = rsqrtf(1.f + 1e-5f);
#pragma unroll
        for (int mi = 0; mi < 4; ++mi) {
            const int r0 = mW + mi * 16 + g8, r1 = r0 + 8;
            const float s0 = gam[r0] * rs, b0 = fmaf(bias[r0], s0, bet[r0]);
            const float s1 = gam[r1] * rs, b1 = fmaf(bias[r1], s1, bet[r1]);
#pragma unroll
            for (int ni = 0; ni < 4; ++ni) {
                const int c = nW + ni * 8 + tg * 2;
                stage[c][r0]     = fmaxf(fmaf(acc[mi][ni][0], s0, b0), 0.f);
                stage[c + 1][r0] = fmaxf(fmaf(acc[mi][ni][1], s0, b0), 0.f);
                stage[c][r1]     = fmaxf(fmaf(acc[mi][ni][2], s1, b1), 0.f);
                stage[c + 1][r1] = fmaxf(fmaf(acc[mi][ni][3], s1, b1), 0.f);
            }
        }
        __syncthreads();
        for (int e = tid; e < 16384; e += 256) {
            int nn = e >> 7, m = e & 127;
            float v = stage[nn][m];
            bf16 h = __float2bfloat16(v);
            bf16 l = __float2bfloat16(v - __bfloat162float(h));
            size_t o = (size_t)(n0 + nn) * K3F;
            O1[o + m]       = h;
            O1[o + 128 + m] = PAT ? l : h;
            O1[o + 256 + m] = PAT ? h : l;
        }
    } else if (EPI == 1) {
#pragma unroll
        for (int mi = 0; mi < 4; ++mi) {
            const int r0 = mW + mi * 16 + g8;
            const float bs0 = bias[r0], bs1 = bias[r0 + 8];
#pragma unroll
            for (int ni = 0; ni < 4; ++ni) {
                const int n = n0 + nW + ni * 8 + tg * 2;
                float v0 = acc[mi][ni][0] + bs0, v1 = acc[mi][ni][1] + bs0;
                float v2 = acc[mi][ni][2] + bs1, v3 = acc[mi][ni][3] + bs1;
                __nv_bfloat162 h01 = __floats2bfloat162_rn(v0, v1);
                __nv_bfloat162 h23 = __floats2bfloat162_rn(v2, v3);
                float2 f01 = __bfloat1622float2(h01);
                float2 f23 = __bfloat1622float2(h23);
                __nv_bfloat162 l01 = __floats2bfloat162_rn(v0 - f01.x, v1 - f01.y);
                __nv_bfloat162 l23 = __floats2bfloat162_rn(v2 - f23.x, v3 - f23.y);
                *(__nv_bfloat162*)&O1[(size_t)r0 * NN + n]       = h01;
                *(__nv_bfloat162*)&O2[(size_t)r0 * NN + n]       = l01;
                *(__nv_bfloat162*)&O1[(size_t)(r0 + 8) * NN + n] = h23;
                *(__nv_bfloat162*)&O2[(size_t)(r0 + 8) * NN + n] = l23;
            }
        }
    } else {
#pragma unroll
        for (int mi = 0; mi < 4; ++mi) {
            const int r0 = m0 + mW + mi * 16 + g8;
            const float bs0 = bias[r0], bs1 = bias[r0 + 8];
#pragma unroll
            for (int ni = 0; ni < 4; ++ni) {
                const int n = n0 + nW + ni * 8 + tg * 2;
                const size_t i0r = (size_t)r0 * NN + n, i1r = (size_t)(r0 + 8) * NN + n;
                float2 rs0 = *(const float2*)&resid[i0r];
                float2 rs1 = *(const float2*)&resid[i1r];
                *(float2*)&Cf[i0r] = make_float2(acc[mi][ni][0] + bs0 + rs0.x,
                                                 acc[mi][ni][1] + bs0 + rs0.y);
                *(float2*)&Cf[i1r] = make_float2(acc[mi][ni][2] + bs1 + rs1.x,
                                                 acc[mi][ni][3] + bs1 + rs1.y);
            }
        }
    }
}

// ---------------------------------------------------------------------------
// Score: E[j,n] = exp(alpha * <faT[j,:], fqT[n,:]>), packed K=384.
// Also per-tile column partial sums PS.
// ---------------------------------------------------------------------------
__global__ void __launch_bounds__(256, 1)
hmma_score(const bf16* __restrict__ A, const bf16* __restrict__ B, size_t sF,
           float* __restrict__ E, float* __restrict__ PS, float alpha)
{
    extern __shared__ char smem[];
    const uint32_t sb = smem_u32(smem);
    const int tid = threadIdx.x, wid = tid >> 5, lane = tid & 31;
    const int b = blockIdx.z;
    const int i0 = blockIdx.y * 128, j0 = blockIdx.x * 128;
    A += (size_t)b * sF + (size_t)i0 * K3F;
    B += (size_t)b * sF + (size_t)j0 * K3F;
    E += (size_t)b * NN * NN;

    const int mW = (wid & 1) * 64, nW = (wid >> 1) * 32;
    float acc[4][4][4];
#pragma unroll
    for (int i = 0; i < 4; ++i)
#pragma unroll
        for (int j = 0; j < 4; ++j)
#pragma unroll
            for (int k = 0; k < 4; ++k) acc[i][j][k] = 0.f;

    const uint32_t oA[2] = { sb, sb + 32768 };
    const uint32_t oB[2] = { sb + 16384, sb + 49152 };
    tile_ld(oA[0], A, K3F, tid);
    tile_ld(oB[0], B, K3F, tid);
    asm volatile("cp.async.commit_group;" ::: "memory");

    const int li8 = lane & 7, sel = lane >> 3;
    int buf = 0;
    for (int c = 0; c < 6; ++c) {
        if (c + 1 < 6) {
            tile_ld(oA[buf ^ 1], A + (size_t)(c + 1) * 64, K3F, tid);
            tile_ld(oB[buf ^ 1], B + (size_t)(c + 1) * 64, K3F, tid);
            asm volatile("cp.async.commit_group;" ::: "memory");
            asm volatile("cp.async.wait_group 1;" ::: "memory");
        } else {
            asm volatile("cp.async.wait_group 0;" ::: "memory");
        }
        __syncthreads();
        const uint32_t ab = oA[buf], bb = oB[buf];
#pragma unroll
        for (int ks = 0; ks < 4; ++ks) {
            const int kb = ks * 32;
            uint32_t af[4][4], bfr[2][4];
#pragma unroll
            for (int mi = 0; mi < 4; ++mi) {
                int row = mW + mi * 16 + li8 + (sel & 1) * 8;
                uint32_t o = (uint32_t)(row * 128 + kb + (sel >> 1) * 16);
                o ^= (o >> 3) & 0x70;
                LDSM4(af[mi], ab + o);
            }
#pragma unroll
            for (int nq = 0; nq < 2; ++nq) {
                int row = nW + nq * 16 + li8 + (sel >> 1) * 8;
                uint32_t o = (uint32_t)(row * 128 + kb + (sel & 1) * 16);
                o ^= (o >> 3) & 0x70;
                LDSM4(bfr[nq], bb + o);
            }
#pragma unroll
            for (int mi = 0; mi < 4; ++mi)
#pragma unroll
                for (int ni = 0; ni < 4; ++ni)
                    MMA(acc[mi][ni], af[mi],
                        bfr[ni >> 1][(ni & 1) * 2], bfr[ni >> 1][(ni & 1) * 2 + 1]);
        }
        __syncthreads();
        buf ^= 1;
    }

    const int g8 = lane >> 2, tg = lane & 3;
    float ev[4][4][4];
#pragma unroll
    for (int mi = 0; mi < 4; ++mi)
#pragma unroll
        for (int ni = 0; ni < 4; ++ni)
#pragma unroll
            for (int k = 0; k < 4; ++k)
                ev[mi][ni][k] = __expf(acc[mi][ni][k] * alpha);
#pragma unroll
    for (int mi = 0; mi < 4; ++mi)
#pragma unroll
        for (int ni = 0; ni < 4; ++ni) {
            const int r  = i0 + mW + mi * 16 + g8;
            const int cN = j0 + nW + ni * 8 + tg * 2;
            *(float2*)&E[(size_t)r * NN + cN]       = make_float2(ev[mi][ni][0], ev[mi][ni][1]);
            *(float2*)&E[(size_t)(r + 8) * NN + cN] = make_float2(ev[mi][ni][2], ev[mi][ni][3]);
        }
    float cs[8];
#pragma unroll
    for (int ni = 0; ni < 4; ++ni)
#pragma unroll
        for (int par = 0; par < 2; ++par) {
            float s = 0.f;
#pragma unroll
            for (int mi = 0; mi < 4; ++mi)
                s += ev[mi][ni][par] + ev[mi][ni][2 + par];
            cs[ni * 2 + par] = s;
        }
#pragma unroll
    for (int o = 4; o <= 16; o <<= 1)
#pragma unroll
        for (int e = 0; e < 8; ++e)
            cs[e] += __shfl_xor_sync(0xffffffffu, cs[e], o);
    float* sP = (float*)smem;
    if (g8 == 0) {
#pragma unroll
        for (int ni = 0; ni < 4; ++ni)
#pragma unroll
            for (int par = 0; par < 2; ++par)
                sP[(wid & 1) * 128 + nW + ni * 8 + tg * 2 + par] = cs[ni * 2 + par];
    }
    __syncthreads();
    if (tid < 128)
        PS[((size_t)(b * NTILE + blockIdx.y)) * NN + j0 + tid] = sP[tid] + sP[128 + tid];
}

// inv[b][n] = 1 / sum_t PS[b][t][n]
__global__ void __launch_bounds__(256)
finalize_inv(const float* __restrict__ PS, float* __restrict__ inv)
{
    const int b = blockIdx.z;
    const int n = blockIdx.x * 256 + threadIdx.x;
    float s = 0.f;
#pragma unroll
    for (int t = 0; t < NTILE; ++t)
        s += PS[((size_t)(b * NTILE + t)) * NN + n];
    inv[b * NN + n] = 1.f / s;
}

// ---------------------------------------------------------------------------
// Fused apply: om[m,j] = sum_n g[m,n] * (E[j,n]*inv[n]); 3-term bf16, K=2304.
// Emits OmT packed [j, K3F] (hi,hi,lo) via smem transpose.
// ---------------------------------------------------------------------------
__global__ void __launch_bounds__(256, 1)
apply_fused(const bf16* __restrict__ Ghi, const bf16* __restrict__ Glo,
            const float* __restrict__ E, const float* __restrict__ inv,
            bf16* __restrict__ OmT)
{
    extern __shared__ char smem[];
    const uint32_t sb = smem_u32(smem);
    const int tid = threadIdx.x, wid = tid >> 5, lane = tid & 31;
    const int b = blockIdx.z;
    const int j0 = blockIdx.x * 128;
    Ghi += (size_t)b * MD * NN;
    Glo += (size_t)b * MD * NN;
    E   += (size_t)b * NN * NN + (size_t)j0 * NN;
    OmT += (size_t)b * NN * K3F;
    const float* invp = inv + (size_t)b * NN;

    const uint32_t A0 = 0, A1 = 32768, E0 = 65536, E1 = 98304,
                   S0 = 131072, S1 = 165888;
    const int mW = (wid & 1) * 64, nW = (wid >> 1) * 32;

    float acc[4][4][4];
#pragma unroll
    for (int i = 0; i < 4; ++i)
#pragma unroll
        for (int j = 0; j < 4; ++j)
#pragma unroll
            for (int k = 0; k < 4; ++k) acc[i][j][k] = 0.f;

    tile_ld(sb + A0,         Ghi, NN, tid);
    tile_ld(sb + A0 + 16384, Glo, NN, tid);
    stage_ld(sb + S0, E, tid);
    asm volatile("cp.async.commit_group;" ::: "memory");
    asm volatile("cp.async.wait_group 0;" ::: "memory");
    __syncthreads();
    cvt_tile(sb + S0, sb + E0, tid, invp);
    tile_ld(sb + A1,         Ghi + 64, NN, tid);
    tile_ld(sb + A1 + 16384, Glo + 64, NN, tid);
    stage_ld(sb + S1, E + 64, tid);
    asm volatile("cp.async.commit_group;" ::: "memory");
    __syncthreads();

    const int li8 = lane & 7, sel = lane >> 3;
    for (int c = 0; c < 36; ++c) {
        const uint32_t Ab = (c & 1) ? A1 : A0;
        const uint32_t Eb = (c & 1) ? E1 : E0;
#pragma unroll
        for (int ks = 0; ks < 4; ++ks) {
            const int kb = ks * 32;
            uint32_t ah[4][4], al[4][4], bh[2][4], bl[2][4];
#pragma unroll
            for (int mi = 0; mi < 4; ++mi) {
                int row = mW + mi * 16 + li8 + (sel & 1) * 8;
                uint32_t o = (uint32_t)(row * 128 + kb + (sel >> 1) * 16);
                o ^= (o >> 3) & 0x70;
                LDSM4(ah[mi], Ab + sb + o);
                LDSM4(al[mi], Ab + sb + 16384 + o);
            }
#pragma unroll
            for (int nq = 0; nq < 2; ++nq) {
                int row = nW + nq * 16 + li8 + (sel >> 1) * 8;
                uint32_t o = (uint32_t)(row * 128 + kb + (sel & 1) * 16);
                o ^= (o >> 3) & 0x70;
                LDSM4(bh[nq], Eb + sb + o);
                LDSM4(bl[nq], Eb + sb + 16384 + o);
            }
#pragma unroll
            for (int mi = 0; mi < 4; ++mi)
#pragma unroll
                for (int ni = 0; ni < 4; ++ni) {
                    const int q = ni >> 1, p = (ni & 1) * 2;
                    MMA(acc[mi][ni], ah[mi], bh[q][p], bh[q][p + 1]);
                    MMA(acc[mi][ni], ah[mi], bl[q][p], bl[q][p + 1]);
                    MMA(acc[mi][ni], al[mi], bh[q][p], bh[q][p + 1]);
                }
        }
        if (c + 1 < 36) {
            asm volatile("cp.async.wait_group 0;" ::: "memory");
            __syncthreads();
            const uint32_t Sq = (c & 1) ? S0 : S1;
            const uint32_t Eq = (c & 1) ? E0 : E1;
            cvt_tile(sb + Sq, sb + Eq, tid, invp + (size_t)(c + 1) * 64);
            if (c + 2 < 36) {
                const uint32_t Ap = (c & 1) ? A1 : A0;
                const uint32_t Sp = (c & 1) ? S1 : S0;
                tile_ld(sb + Ap,         Ghi + (size_t)(c + 2) * 64, NN, tid);
                tile_ld(sb + Ap + 16384, Glo + (size_t)(c + 2) * 64, NN, tid);
                stage_ld(sb + Sp, E + (size_t)(c + 2) * 64, tid);
                asm volatile("cp.async.commit_group;" ::: "memory");
            }
            __syncthreads();
        }
    }

    // epilogue: stage[j_local][m], then packed split write (hi,hi,lo)
    __syncthreads();
    float (*stage)[129] = (float(*)[129])smem;
    const int g8 = lane >> 2, tg = lane & 3;
#pragma unroll
    for (int mi = 0; mi < 4; ++mi) {
        const int r0 = mW + mi * 16 + g8;
#pragma unroll
        for (int ni = 0; ni < 4; ++ni) {
            const int c = nW + ni * 8 + tg * 2;
            stage[c][r0]         = acc[mi][ni][0];
            stage[c + 1][r0]     = acc[mi][ni][1];
            stage[c][r0 + 8]     = acc[mi][ni][2];
            stage[c + 1][r0 + 8] = acc[mi][ni][3];
        }
    }
    __syncthreads();
    for (int e = tid; e < 16384; e += 256) {
        int jl = e >> 7, m = e & 127;
        float v = stage[jl][m];
        bf16 h = __float2bfloat16(v);
        bf16 l = __float2bfloat16(v - __bfloat162float(h));
        size_t o = (size_t)(j0 + jl) * K3F;
        OmT[o + m]       = h;
        OmT[o + 128 + m] = h;
        OmT[o + 256 + m] = l;
    }
}

// ---------------------------------------------------------------------------
// x split-transpose: X fp32 [C,N] per batch -> XT bf16 [N, K3C] (hi,hi,lo)
// ---------------------------------------------------------------------------
__global__ void __launch_bounds__(256)
xsplitT(const float* __restrict__ X, bf16* __restrict__ XT)
{
    extern __shared__ char smem[];
    float (*stage)[129] = (float(*)[129])smem;
    const int b = blockIdx.z;
    const int c0 = blockIdx.y * 128, n0 = blockIdx.x * 128;
    X  += (size_t)b * CC * NN;
    XT += (size_t)b * NN * K3C;
    const int tid = threadIdx.x;

    for (int e = tid; e < 16384; e += 256) {
        int cc = e >> 7, nn = e & 127;
        stage[nn][cc] = X[(size_t)(c0 + cc) * NN + n0 + nn];
    }
    __syncthreads();
    for (int e = tid; e < 16384; e += 256) {
        int nn = e >> 7, cc = e & 127;
        float v = stage[nn][cc];
        bf16 h = __float2bfloat16(v);
        bf16 l = __float2bfloat16(v - __bfloat162float(h));
        size_t o = (size_t)(n0 + nn) * K3C;
        XT[o + c0 + cc]        = h;
        XT[o + 512 + c0 + cc]  = h;
        XT[o + 1024 + c0 + cc] = l;
    }
}

// weight split: W fp32 [M,K] -> O bf16 [M, 3K] (hi,lo,hi)
__global__ void __launch_bounds__(256)
wsplit(const float* __restrict__ W, bf16* __restrict__ O, int K)
{
    const int idx = blockIdx.x * 256 + threadIdx.x;
    const int m = idx / K, k = idx % K;
    float v = W[idx];
    bf16 h = __float2bfloat16(v);
    bf16 l = __float2bfloat16(v - __bfloat162float(h));
    const size_t o = (size_t)m * 3 * K;
    O[o + k]         = h;
    O[o + K + k]     = l;
    O[o + 2 * K + k] = h;
}

// ---------------------------------------------------------------------------

extern "C" void kernel_launch(void* const* d_in, const int* in_sizes, int n_in,
                              void* d_out, int out_size)
{
    const float* x    = (const float*)d_in[0];
    const float* x_h  = (const float*)d_in[1];
    const float* x_v  = (const float*)d_in[2];
    const float* Wa   = (const float*)d_in[3];
    const float* ba   = (const float*)d_in[4];
    const float* ga   = (const float*)d_in[5];
    const float* ta   = (const float*)d_in[6];
    const float* Wv   = (const float*)d_in[7];
    const float* bv   = (const float*)d_in[8];
    const float* gv   = (const float*)d_in[9];
    const float* tv   = (const float*)d_in[10];
    const float* Wgav = (const float*)d_in[11];
    const float* bgav = (const float*)d_in[12];
    const float* Wgah = (const float*)d_in[13];
    const float* bgah = (const float*)d_in[14];
    const float* Wfav = (const float*)d_in[15];
    const float* bfav = (const float*)d_in[16];
    const float* Wfah = (const float*)d_in[17];
    const float* bfah = (const float*)d_in[18];
    float* out = (float*)d_out;

    float *E, *ps, *inv;
    bf16 *xT, *xvT, *xhT, *faT, *fvT, *fhT;
    bf16 *Wap, *Wvp, *Wgavp, *Wgahp, *Wfavp, *Wfahp;
    bf16 *gavhi, *gavlo, *gahhi, *gahlo, *OmT;
    cudaGetSymbolAddress((void**)&E,     d_E);
    cudaGetSymbolAddress((void**)&ps,    d_ps);
    cudaGetSymbolAddress((void**)&inv,   d_inv);
    cudaGetSymbolAddress((void**)&xT,    d_xT);
    cudaGetSymbolAddress((void**)&xvT,   d_xvT);
    cudaGetSymbolAddress((void**)&xhT,   d_xhT);
    cudaGetSymbolAddress((void**)&faT,   d_faT);
    cudaGetSymbolAddress((void**)&fvT,   d_fvT);
    cudaGetSymbolAddress((void**)&fhT,   d_fhT);
    cudaGetSymbolAddress((void**)&Wap,   d_Wap);
    cudaGetSymbolAddress((void**)&Wvp,   d_Wvp);
    cudaGetSymbolAddress((void**)&Wgavp, d_Wgavp);
    cudaGetSymbolAddress((void**)&Wgahp, d_Wgahp);
    cudaGetSymbolAddress((void**)&Wfavp, d_Wfavp);
    cudaGetSymbolAddress((void**)&Wfahp, d_Wfahp);
    cudaGetSymbolAddress((void**)&gavhi, d_gavhi);
    cudaGetSymbolAddress((void**)&gavlo, d_gavlo);
    cudaGetSymbolAddress((void**)&gahhi, d_gahhi);
    cudaGetSymbolAddress((void**)&gahlo, d_gahlo);
    cudaGetSymbolAddress((void**)&OmT,   d_OmT);

    const int SMEM_CV = 66560;    // operands 64KB / stage 66048
    const int SMEM_SC = 65536;
    const int SMEM_AP = 200704;
    const int SMEM_ST = 66048;
    cudaFuncSetAttribute(hmma_conv<0,0>, cudaFuncAttributeMaxDynamicSharedMemorySize, SMEM_CV);
    cudaFuncSetAttribute(hmma_conv<0,1>, cudaFuncAttributeMaxDynamicSharedMemorySize, SMEM_CV);
    cudaFuncSetAttribute(hmma_conv<1,0>, cudaFuncAttributeMaxDynamicSharedMemorySize, SMEM_CV);
    cudaFuncSetAttribute(hmma_conv<2,0>, cudaFuncAttributeMaxDynamicSharedMemorySize, SMEM_CV);
    cudaFuncSetAttribute(hmma_score,     cudaFuncAttributeMaxDynamicSharedMemorySize, SMEM_SC);
    cudaFuncSetAttribute(apply_fused,    cudaFuncAttributeMaxDynamicSharedMemorySize, SMEM_AP);
    cudaFuncSetAttribute(xsplitT,        cudaFuncAttributeMaxDynamicSharedMemorySize, SMEM_ST);

    const size_t sX  = (size_t)CC * NN;
    const size_t sXT = (size_t)NN * K3C;
    const size_t sF  = (size_t)NN * K3F;
    const size_t sG  = (size_t)MD * NN;
    const size_t halfOut = (size_t)BB * CC * NN;
    const float alpha = 0.08838834764831845f;  // 128^-0.5

    dim3 blk(256);
    dim3 gXT   (NN / 128, CC / 128, BB);
    dim3 gConv (NN / 128, 1, BB);
    dim3 gScore(NN / 128, NN / 128, BB);
    dim3 gApply(NN / 128, 1, BB);
    dim3 gOut  (NN / 128, CC / 128, BB);
    dim3 gInv  (NN / 256, 1, BB);

    // Phase 0: pack inputs + weights
    xsplitT<<<gXT, blk, SMEM_ST>>>(x,   xT);
    xsplitT<<<gXT, blk, SMEM_ST>>>(x_v, xvT);
    xsplitT<<<gXT, blk, SMEM_ST>>>(x_h, xhT);
    wsplit<<<(MD * CC) / 256, blk>>>(Wa,   Wap,   CC);
    wsplit<<<(MD * CC) / 256, blk>>>(Wv,   Wvp,   CC);
    wsplit<<<(MD * CC) / 256, blk>>>(Wgav, Wgavp, CC);
    wsplit<<<(MD * CC) / 256, blk>>>(Wgah, Wgahp, CC);
    wsplit<<<(CC * MD) / 256, blk>>>(Wfav, Wfavp, MD);
    wsplit<<<(CC * MD) / 256, blk>>>(Wfah, Wfahp, MD);

    // Phase 1: input convs (HMMA)
    hmma_conv<0,1><<<gConv, blk, SMEM_CV>>>(Wap,   xT,  sXT, K3C, nullptr, 0, faT, nullptr, sF, ba,   ga, ta, nullptr, 0);
    hmma_conv<0,0><<<gConv, blk, SMEM_CV>>>(Wvp,   xvT, sXT, K3C, nullptr, 0, fvT, nullptr, sF, bv,   gv, tv, nullptr, 0);
    hmma_conv<0,0><<<gConv, blk, SMEM_CV>>>(Wvp,   xhT, sXT, K3C, nullptr, 0, fhT, nullptr, sF, bv,   gv, tv, nullptr, 0);
    hmma_conv<1,0><<<gConv, blk, SMEM_CV>>>(Wgavp, xT,  sXT, K3C, nullptr, 0, gavhi, gavlo, sG, bgav, nullptr, nullptr, nullptr, 0);
    hmma_conv<1,0><<<gConv, blk, SMEM_CV>>>(Wgahp, xT,  sXT, K3C, nullptr, 0, gahhi, gahlo, sG, bgah, nullptr, nullptr, nullptr, 0);

    // Pass ah -> o_h
    hmma_score<<<gScore, blk, SMEM_SC>>>(faT, fhT, sF, E, ps, alpha);
    finalize_inv<<<gInv, blk>>>(ps, inv);
    apply_fused<<<gApply, blk, SMEM_AP>>>(gahhi, gahlo, E, inv, OmT);
    hmma_conv<2,0><<<gOut, blk, SMEM_CV>>>(Wfahp, OmT, sF, K3F, out, sX, nullptr, nullptr, 0, bfah, nullptr, nullptr, x, sX);

    // Pass av -> o_v
    hmma_score<<<gScore, blk, SMEM_SC>>>(faT, fvT, sF, E, ps, alpha);
    finalize_inv<<<gInv, blk>>>(ps, inv);
    apply_fused<<<gApply, blk, SMEM_AP>>>(gavhi, gavlo, E, inv, OmT);
    hmma_conv<2,0><<<gOut, blk, SMEM_CV>>>(Wfavp, OmT, sF, K3F, out + halfOut, sX, nullptr, nullptr, 0, bfav, nullptr, nullptr, x, sX);
}